// round 17
// baseline (speedup 1.0000x reference)
#include <cuda_runtime.h>
#include <cstdint>
#include <cstddef>
#include <climits>

#define NPTS     8192
#define BATCH    8
#define MSEL     4096        // ceil(0.5 * 8192)
#define NTHREADS 256
#define NWARPS   8
#define PPT      32          // points per thread
#define NPAIR    16          // f32x2 pairs per thread
// smem floats: packed pos pairs [NPTS*6] + fused keys [2][8] u64 (32 floats) + idx list [MSEL]
#define SMEM_FLOATS (NPTS * 6 + 32 + MSEL)
#define SMEM_BYTES  (SMEM_FLOATS * 4)

// Selected indices, produced by FPS kernel, consumed by gather kernel.
__device__ int g_sel_idx[BATCH * MSEL];

// ---------------- f32x2 packed helpers (sm_100+) ----------------
__device__ __forceinline__ unsigned long long pack2(float lo, float hi) {
    unsigned long long r;
    asm("mov.b64 %0, {%1, %2};" : "=l"(r) : "f"(lo), "f"(hi));
    return r;
}
__device__ __forceinline__ void unpack2(unsigned long long v, float& lo, float& hi) {
    asm("mov.b64 {%0, %1}, %2;" : "=f"(lo), "=f"(hi) : "l"(v));
}
__device__ __forceinline__ unsigned long long add2(unsigned long long a, unsigned long long b) {
    unsigned long long r;
    asm("add.rn.f32x2 %0, %1, %2;" : "=l"(r) : "l"(a), "l"(b));
    return r;
}
__device__ __forceinline__ unsigned long long mul2(unsigned long long a, unsigned long long b) {
    unsigned long long r;
    asm("mul.rn.f32x2 %0, %1, %2;" : "=l"(r) : "l"(a), "l"(b));
    return r;
}
__device__ __forceinline__ unsigned long long umax64(unsigned long long a, unsigned long long b) {
    return a > b ? a : b;
}

extern __shared__ float smem[];

// ---------------- FPS kernel: one CTA (256 thr) per batch ----------------
__global__ __launch_bounds__(NTHREADS, 1)
void fps_kernel(const float* __restrict__ points, float* __restrict__ dp_out)
{
    float*              s_pos2 = smem;                                   // [NPTS*6]
    unsigned long long* s_comb = (unsigned long long*)(smem + NPTS * 6); // [2][8] keys
    int*                s_idx  = (int*)(smem + NPTS * 6 + 32);           // [MSEL]

    const int b    = blockIdx.x;
    const int tid  = threadIdx.x;
    const int lane = tid & 31;
    const int warp = tid >> 5;                        // 0..7
    const float* p = points + (size_t)b * NPTS * 3;

    // Stage duplicated point pairs to shared (coalesced gmem reads).
    for (int k = tid; k < NPTS * 3; k += NTHREADS) {
        float v = p[k];
        int   i = k / 3, c = k - 3 * i;
        s_pos2[6 * i + 2 * c]     = v;
        s_pos2[6 * i + 2 * c + 1] = v;
    }
    if (tid == 0) s_idx[0] = 0;
    __syncthreads();

    // Register-resident NEGATED coords: pair j holds ids (2j)*256+tid (lo), (2j+1)*256+tid (hi).
    unsigned long long NX[NPAIR], NY[NPAIR], NZ[NPAIR];
    float mind[PPT];
#pragma unroll
    for (int i = 0; i < PPT; i++) mind[i] = 1e10f;
#pragma unroll
    for (int j = 0; j < NPAIR; j++) {
        int i0 = (2 * j) * NTHREADS + tid;
        int i1 = (2 * j + 1) * NTHREADS + tid;
        NX[j] = pack2(-s_pos2[6 * i0 + 0], -s_pos2[6 * i1 + 0]);
        NY[j] = pack2(-s_pos2[6 * i0 + 2], -s_pos2[6 * i1 + 2]);
        NZ[j] = pack2(-s_pos2[6 * i0 + 4], -s_pos2[6 * i1 + 4]);
    }

    int gidx = 0;  // step 0: deterministic start at index 0
    int buf  = 0;

    for (int step = 1; step < MSEL; ++step) {
        // Broadcast the selected point as pre-duplicated 64-bit pairs (3x LDS.64).
        const unsigned long long* lp =
            (const unsigned long long*)(s_pos2 + 6 * gidx);
        unsigned long long lx2 = lp[0];
        unsigned long long ly2 = lp[1];
        unsigned long long lz2 = lp[2];

        // XLA-exact: (-x + lx)^2 == (x - lx)^2 bit-exactly; every op rounded, no FMA.
#pragma unroll
        for (int j = 0; j < NPAIR; j++) {
            unsigned long long dx = add2(NX[j], lx2);
            unsigned long long dy = add2(NY[j], ly2);
            unsigned long long dz = add2(NZ[j], lz2);
            unsigned long long sx = mul2(dx, dx);
            unsigned long long sy = mul2(dy, dy);
            unsigned long long sz = mul2(dz, dz);
            unsigned long long dd = add2(add2(sx, sy), sz);
            float d0, d1;
            unpack2(dd, d0, d1);
            mind[2 * j]     = fminf(mind[2 * j], d0);
            mind[2 * j + 1] = fminf(mind[2 * j + 1], d1);
        }

        // Max-tree over the 32 running minima (depth 5).
        float u[8];
#pragma unroll
        for (int g = 0; g < 8; g++)
            u[g] = fmaxf(fmaxf(mind[4 * g], mind[4 * g + 1]),
                         fmaxf(mind[4 * g + 2], mind[4 * g + 3]));
        float vmax = fmaxf(fmaxf(fmaxf(u[0], u[1]), fmaxf(u[2], u[3])),
                           fmaxf(fmaxf(u[4], u[5]), fmaxf(u[6], u[7])));

        // Stage A: warp max value + lowest tied index within warp.
        // 4 interleaved 8-deep SEL chains (short serial depth), exact lowest-index.
        unsigned vb   = __float_as_uint(vmax);  // nonneg floats: uint order == float order
        unsigned wmax = __reduce_max_sync(0xffffffffu, vb);
        int cand = INT_MAX;
        if (vb == wmax) {
            int c0 = INT_MAX, c1 = INT_MAX, c2c = INT_MAX, c3 = INT_MAX;
#pragma unroll
            for (int i = 7; i >= 0; i--) {
                if (__float_as_uint(mind[i])      == vb) c0  = i * NTHREADS + tid;
                if (__float_as_uint(mind[i + 8])  == vb) c1  = (i + 8) * NTHREADS + tid;
                if (__float_as_uint(mind[i + 16]) == vb) c2c = (i + 16) * NTHREADS + tid;
                if (__float_as_uint(mind[i + 24]) == vb) c3  = (i + 24) * NTHREADS + tid;
            }
            cand = min(min(c0, c1), min(c2c, c3));
        }
        int wmin_idx = __reduce_min_sync(0xffffffffu, cand);

        // Fused key: (value << 32) | (8191 - idx). u64 max == (max value, lowest idx).
        if (lane == 0)
            s_comb[buf * 8 + warp] =
                ((unsigned long long)wmax << 32) | (unsigned)(8191 - wmin_idx);
        __syncthreads();  // single barrier per iteration

        // Stage B: in-register max-tree over the 8 fused keys (broadcast LDS.128 x4).
        const ulonglong2* cb = (const ulonglong2*)(s_comb + buf * 8);
        ulonglong2 p0 = cb[0], p1 = cb[1], p2 = cb[2], p3 = cb[3];
        unsigned long long m0 = umax64(p0.x, p0.y);
        unsigned long long m1 = umax64(p1.x, p1.y);
        unsigned long long m2 = umax64(p2.x, p2.y);
        unsigned long long m3 = umax64(p3.x, p3.y);
        unsigned long long mm = umax64(umax64(m0, m1), umax64(m2, m3));
        gidx = 8191 - (int)(unsigned)mm;

        if (tid == 0) s_idx[step] = gidx;   // 1 predicated STS
        buf ^= 1;                           // double-buffer: next step uses other slots
    }
    __syncthreads();  // s_idx complete

    // Batched writeout of indices + selected points (off the critical loop).
    for (int r = tid; r < MSEL; r += NTHREADS) {
        int id = s_idx[r];
        g_sel_idx[b * MSEL + r] = id;
        size_t o = ((size_t)b * MSEL + r) * 3;
        dp_out[o + 0] = s_pos2[6 * id + 0];
        dp_out[o + 1] = s_pos2[6 * id + 2];
        dp_out[o + 2] = s_pos2[6 * id + 4];
    }
}

// ---------------- Feature gather: [B, m, 256] float32 ----------------
// 256 threads/block -> 8 rows/block; 32 threads/row, each thread 2 float4 (MLP=2).
__global__ void gather_kernel(const float* __restrict__ feat, float* __restrict__ df_out)
{
    int r = blockIdx.x * 8 + (threadIdx.x >> 5);
    int c = threadIdx.x & 31;
    int b = r >> 12;  // r / 4096
    int id = g_sel_idx[r];
    const float4* src = (const float4*)(feat + ((size_t)b * NPTS + id) * 256);
    float4 v0 = src[c];
    float4 v1 = src[c + 32];
    float4* dst = (float4*)df_out + (size_t)r * 64;
    dst[c]      = v0;
    dst[c + 32] = v1;
}

extern "C" void kernel_launch(void* const* d_in, const int* in_sizes, int n_in,
                              void* d_out, int out_size)
{
    (void)n_in; (void)out_size;
    const float* points;
    const float* feats;
    if (in_sizes[0] == BATCH * NPTS * 3) {
        points = (const float*)d_in[0];
        feats  = (const float*)d_in[1];
    } else {
        points = (const float*)d_in[1];
        feats  = (const float*)d_in[0];
    }

    float* out = (float*)d_out;
    float* dp  = out;                              // [B, m, 3]
    float* df  = out + (size_t)BATCH * MSEL * 3;   // [B, m, 256]

    cudaFuncSetAttribute(fps_kernel, cudaFuncAttributeMaxDynamicSharedMemorySize,
                         SMEM_BYTES);
    fps_kernel<<<BATCH, NTHREADS, SMEM_BYTES>>>(points, dp);
    gather_kernel<<<(BATCH * MSEL) / 8, 256>>>(feats, df);
}